// round 4
// baseline (speedup 1.0000x reference)
#include <cuda_runtime.h>
#include <cstdint>

#define T_LEN  4096
#define BATCH  32
#define AD     256
#define VD     256
#define TILE_T 128
#define NTILE  (T_LEN / TILE_T)   // 32
#define KC     32
#define NKC    (VD / KC)          // 8
#define ASTR   36                 // padded row stride (floats): 144B, 16B-aligned, conflict-free
#define ASZ    (TILE_T * ASTR)    // 4608 floats
#define BSZ    (AD * ASTR)        // 9216 floats
#define SMEM_FLOATS (2 * ASZ + 2 * BSZ)
#define SMEM_BYTES  (SMEM_FLOATS * 4)   // 110592

// ---- device scratch (no runtime allocation allowed) ----
__device__ float g_s[BATCH * AD];              // q-proj + bq + bv
__device__ float g_e[BATCH * T_LEN];           // raw scores
__device__ float g_m[BATCH * NTILE];           // tile max
__device__ float g_l[BATCH * NTILE];           // tile sum exp
__device__ float g_cp[BATCH * NTILE * VD];     // tile partial context

// ---- helpers ----
__device__ __forceinline__ void cp16(uint32_t dst, const float* src) {
    asm volatile("cp.async.cg.shared.global [%0], [%1], 16;" :: "r"(dst), "l"(src));
}
__device__ __forceinline__ void cp_commit() { asm volatile("cp.async.commit_group;"); }
template <int N> __device__ __forceinline__ void cp_wait() {
    asm volatile("cp.async.wait_group %0;" :: "n"(N));
}

__device__ __forceinline__ void mma_tf32(
    float& d0, float& d1, float& d2, float& d3,
    uint32_t a0, uint32_t a1, uint32_t a2, uint32_t a3,
    uint32_t b0, uint32_t b1)
{
    asm volatile(
        "mma.sync.aligned.m16n8k8.row.col.f32.tf32.tf32.f32 "
        "{%0,%1,%2,%3}, {%4,%5,%6,%7}, {%8,%9}, {%0,%1,%2,%3};"
        : "+f"(d0), "+f"(d1), "+f"(d2), "+f"(d3)
        : "r"(a0), "r"(a1), "r"(a2), "r"(a3), "r"(b0), "r"(b1));
}

// ============================================================================
// K0: s[b,a] = sum_q query[b,q]*Wq[a,q] + bq[a] + bv[a]
// ============================================================================
__global__ void qproj_kernel(const float* __restrict__ query,
                             const float* __restrict__ Wq,
                             const float* __restrict__ bq,
                             const float* __restrict__ bv)
{
    int b = blockIdx.x, a = threadIdx.x;
    __shared__ float q_sm[AD];
    q_sm[a] = query[b * AD + a];
    __syncthreads();
    const float* wrow = Wq + (size_t)a * AD;
    float acc = bq[a] + bv[a];
#pragma unroll 8
    for (int q = 0; q < AD; q++) acc += q_sm[q] * wrow[q];
    g_s[b * AD + a] = acc;
}

// ============================================================================
// K1: per (b, T-tile of 128): keys GEMM (tf32 mma) -> tanh score -> tile
// softmax stats -> partial context. 512 threads = 16 warps in a 4(m)x4(n)
// grid; each warp owns a 32x64 accumulator tile.
// ============================================================================
__global__ void __launch_bounds__(512, 1)
attn_main(const float* __restrict__ values,
          const float* __restrict__ Wv,
          const float* __restrict__ wscore)
{
    extern __shared__ float dsm[];
    const int tid  = threadIdx.x;
    const int lane = tid & 31, warp = tid >> 5;
    const int wm = warp >> 2, wn = warp & 3;
    const int tile = blockIdx.x, b = blockIdx.y;
    const int t0 = tile * TILE_T;

    __shared__ float s_sm[AD], w_sm[AD];
    __shared__ float e_sm[TILE_T], p_sm[TILE_T];
    __shared__ float redm[4], redl[4];
    __shared__ float m_sh;

    if (tid < AD) { s_sm[tid] = g_s[b * AD + tid]; w_sm[tid] = wscore[tid]; }
    if (tid < TILE_T) e_sm[tid] = 0.f;

    const float* vbase = values + ((size_t)b * T_LEN + t0) * VD;
    uint32_t sbase = (uint32_t)__cvta_generic_to_shared(dsm);

    float acc[2][8][4];
#pragma unroll
    for (int i = 0; i < 2; i++)
#pragma unroll
        for (int j = 0; j < 8; j++)
#pragma unroll
            for (int k = 0; k < 4; k++) acc[i][j][k] = 0.f;

    auto load_tile = [&](int buf, int kc) {
        const float* va = vbase + kc * KC;
        const float* wb = Wv + kc * KC;
        // A tile: 128 rows x 32 cols = 1024 x 16B chunks
#pragma unroll
        for (int r = 0; r < 2; r++) {
            int ch = tid + r * 512;
            int row = ch >> 3, seg = ch & 7;
            uint32_t dst = sbase + (uint32_t)((buf * ASZ + row * ASTR + seg * 4) * 4);
            cp16(dst, va + (size_t)row * VD + seg * 4);
        }
        // B tile: 256 rows x 32 cols = 2048 x 16B chunks
#pragma unroll
        for (int r = 0; r < 4; r++) {
            int ch = tid + r * 512;
            int row = ch >> 3, seg = ch & 7;
            uint32_t dst = sbase + (uint32_t)((2 * ASZ + buf * BSZ + row * ASTR + seg * 4) * 4);
            cp16(dst, wb + (size_t)row * VD + seg * 4);
        }
    };

    load_tile(0, 0);
    cp_commit();

    const int kq = lane & 3;
    const int rbase0 = wm * 32 + (lane >> 2);

    for (int kc = 0; kc < NKC; kc++) {
        if (kc + 1 < NKC) load_tile((kc + 1) & 1, kc + 1);
        cp_commit();
        cp_wait<1>();
        __syncthreads();
        const uint32_t* A32 = (const uint32_t*)(dsm + (kc & 1) * ASZ);
        const uint32_t* B32 = (const uint32_t*)(dsm + 2 * ASZ + (kc & 1) * BSZ);
#pragma unroll
        for (int ks = 0; ks < 4; ks++) {
            uint32_t af[2][4];
#pragma unroll
            for (int i = 0; i < 2; i++) {
                int r0 = rbase0 + i * 16;
                af[i][0] = A32[r0 * ASTR + ks * 8 + kq];
                af[i][1] = A32[(r0 + 8) * ASTR + ks * 8 + kq];
                af[i][2] = A32[r0 * ASTR + ks * 8 + kq + 4];
                af[i][3] = A32[(r0 + 8) * ASTR + ks * 8 + kq + 4];
            }
#pragma unroll
            for (int j = 0; j < 8; j++) {
                int n = wn * 64 + j * 8 + (lane >> 2);
                uint32_t b0 = B32[n * ASTR + ks * 8 + kq];
                uint32_t b1 = B32[n * ASTR + ks * 8 + kq + 4];
#pragma unroll
                for (int i = 0; i < 2; i++)
                    mma_tf32(acc[i][j][0], acc[i][j][1], acc[i][j][2], acc[i][j][3],
                             af[i][0], af[i][1], af[i][2], af[i][3], b0, b1);
            }
        }
        __syncthreads();
    }

    // ---- score epilogue: e[t] = sum_a w[a]*tanh(keys[t,a] + s[a]) ----
#pragma unroll
    for (int i = 0; i < 2; i++) {
        float sA = 0.f, sB = 0.f;
#pragma unroll
        for (int j = 0; j < 8; j++) {
            int c0 = wn * 64 + j * 8 + 2 * (lane & 3);
            int c1 = c0 + 1;
            sA += w_sm[c0] * tanhf(acc[i][j][0] + s_sm[c0])
                + w_sm[c1] * tanhf(acc[i][j][1] + s_sm[c1]);
            sB += w_sm[c0] * tanhf(acc[i][j][2] + s_sm[c0])
                + w_sm[c1] * tanhf(acc[i][j][3] + s_sm[c1]);
        }
        sA += __shfl_xor_sync(0xffffffff, sA, 1);
        sA += __shfl_xor_sync(0xffffffff, sA, 2);
        sB += __shfl_xor_sync(0xffffffff, sB, 1);
        sB += __shfl_xor_sync(0xffffffff, sB, 2);
        if ((lane & 3) == 0) {
            int r0 = wm * 32 + i * 16 + (lane >> 2);
            atomicAdd(&e_sm[r0], sA);
            atomicAdd(&e_sm[r0 + 8], sB);
        }
    }
    __syncthreads();

    // ---- tile-local softmax stats ----
    if (tid < TILE_T) {
        float v = e_sm[tid];
#pragma unroll
        for (int o = 16; o > 0; o >>= 1) v = fmaxf(v, __shfl_xor_sync(0xffffffff, v, o));
        if (lane == 0) redm[warp] = v;
    }
    __syncthreads();
    if (tid == 0)
        m_sh = fmaxf(fmaxf(redm[0], redm[1]), fmaxf(redm[2], redm[3]));
    __syncthreads();
    float mt = m_sh;
    if (tid < TILE_T) {
        float e = e_sm[tid];
        float p = __expf(e - mt);
        p_sm[tid] = p;
        g_e[b * T_LEN + t0 + tid] = e;
#pragma unroll
        for (int o = 16; o > 0; o >>= 1) p += __shfl_xor_sync(0xffffffff, p, o);
        if (lane == 0) redl[warp] = p;
    }
    __syncthreads();
    if (tid == 0) {
        g_m[b * NTILE + tile] = mt;
        g_l[b * NTILE + tile] = redl[0] + redl[1] + redl[2] + redl[3];
    }
    __syncthreads();   // p_sm visible; GEMM smem free for reuse

    // ---- partial context: cp[v] = sum_t p[t]*values[b,t0+t,v] (L2 re-read) ----
    {
        int v = tid & 255, half = tid >> 8;
        const float* vp = values + ((size_t)b * T_LEN + t0 + half * 64) * VD + v;
        float ca = 0.f;
#pragma unroll 8
        for (int t = 0; t < 64; t++) ca += p_sm[half * 64 + t] * vp[(size_t)t * VD];
        float* cacc = dsm;   // reuse GEMM smem
        cacc[half * 256 + v] = ca;
        __syncthreads();
        if (tid < VD)
            g_cp[((b * NTILE + tile) << 8) + tid] = cacc[tid] + cacc[256 + tid];
    }
}

// ============================================================================
// K2: per-b combine: global softmax + final a and c.
// out layout: c [B,VD] then a [B,T]   (bv_score dropped: softmax-invariant)
// ============================================================================
__global__ void combine_kernel(float* __restrict__ out)
{
    int b = blockIdx.x, tid = threadIdx.x;
    __shared__ float mt[NTILE], lt[NTILE];
    __shared__ float M_sh, invL_sh;
    if (tid < NTILE) { mt[tid] = g_m[b * NTILE + tid]; lt[tid] = g_l[b * NTILE + tid]; }
    __syncthreads();
    if (tid == 0) {
        float M = -1e30f;
        for (int i = 0; i < NTILE; i++) M = fmaxf(M, mt[i]);
        float L = 0.f;
        for (int i = 0; i < NTILE; i++) L += lt[i] * __expf(mt[i] - M);
        M_sh = M;
        invL_sh = 1.0f / L;
    }
    __syncthreads();
    float M = M_sh, invL = invL_sh;
    float* c_out = out;
    float* a_out = out + BATCH * VD;
    for (int t = tid; t < T_LEN; t += blockDim.x)
        a_out[b * T_LEN + t] = __expf(g_e[b * T_LEN + t] - M) * invL;
    if (tid < VD) {
        float acc = 0.f;
        for (int i = 0; i < NTILE; i++)
            acc += g_cp[((b * NTILE + i) << 8) + tid] * __expf(mt[i] - M);
        c_out[b * VD + tid] = acc * invL;
    }
}

// ============================================================================
// launch
// ============================================================================
extern "C" void kernel_launch(void* const* d_in, const int* in_sizes, int n_in,
                              void* d_out, int out_size)
{
    const float* query  = (const float*)d_in[0];
    const float* values = (const float*)d_in[1];
    const float* Wq     = (const float*)d_in[2];
    const float* bq     = (const float*)d_in[3];
    const float* Wv     = (const float*)d_in[4];
    const float* bv     = (const float*)d_in[5];
    const float* wsc    = (const float*)d_in[6];
    // d_in[7] = bv_score: additive constant inside softmax -> no effect on outputs
    (void)in_sizes; (void)n_in; (void)out_size;
    float* out = (float*)d_out;

    cudaFuncSetAttribute(attn_main, cudaFuncAttributeMaxDynamicSharedMemorySize, SMEM_BYTES);

    qproj_kernel<<<BATCH, AD>>>(query, Wq, bq, bv);
    attn_main<<<dim3(NTILE, BATCH), 512, SMEM_BYTES>>>(values, Wv, wsc);
    combine_kernel<<<BATCH, 256>>>(out);
}

// round 6
// speedup vs baseline: 1.3910x; 1.3910x over previous
#include <cuda_runtime.h>
#include <cuda_fp16.h>
#include <cstdint>

#define T_LEN  4096
#define BATCH  32
#define AD     256
#define VD     256
#define TILE_T 128
#define NTILE  (T_LEN / TILE_T)   // 32
#define KC     32                 // K floats per pipeline chunk
#define NKC    (VD / KC)          // 8

// ---- smem layout (bytes) ----
#define AF32_STRIDE 144           // 32 floats + 16B pad
#define AF32_STAGE  (TILE_T * AF32_STRIDE)        // 18432
#define A2_STRIDE_H2 18           // 16 half2 + 2 pad  (72B rows)
#define A2_BYTES    (TILE_T * A2_STRIDE_H2 * 4)   // 9216
#define B2_STRIDE_H2 20           // 16 half2 + 4 pad  (80B rows)
#define B2_STAGE    (AD * B2_STRIDE_H2 * 4)       // 20480
#define OFF_A2      (2 * AF32_STAGE)              // 36864
#define OFF_B2      (OFF_A2 + A2_BYTES)           // 46080
#define DSMEM_BYTES (OFF_B2 + 2 * B2_STAGE)       // 87040

// ---- device scratch ----
__device__ float   g_s[BATCH * AD];
__device__ float   g_e[BATCH * T_LEN];
__device__ float   g_m[BATCH * NTILE];
__device__ float   g_l[BATCH * NTILE];
__device__ float   g_cp[BATCH * NTILE * VD];
__device__ __half2 g_wh[AD * VD / 2];             // Wv in fp16, row-major [a][k]

// ---- helpers ----
__device__ __forceinline__ void cp16(uint32_t dst, const void* src) {
    asm volatile("cp.async.cg.shared.global [%0], [%1], 16;" :: "r"(dst), "l"(src));
}
__device__ __forceinline__ void cp_commit() { asm volatile("cp.async.commit_group;"); }
template <int N> __device__ __forceinline__ void cp_wait() {
    asm volatile("cp.async.wait_group %0;" :: "n"(N));
}

__device__ __forceinline__ void mma_f16(
    float& d0, float& d1, float& d2, float& d3,
    uint32_t a0, uint32_t a1, uint32_t a2, uint32_t a3,
    uint32_t b0, uint32_t b1)
{
    asm volatile(
        "mma.sync.aligned.m16n8k16.row.col.f32.f16.f16.f32 "
        "{%0,%1,%2,%3}, {%4,%5,%6,%7}, {%8,%9}, {%0,%1,%2,%3};"
        : "+f"(d0), "+f"(d1), "+f"(d2), "+f"(d3)
        : "r"(a0), "r"(a1), "r"(a2), "r"(a3), "r"(b0), "r"(b1));
}

// ============================================================================
// K0a: Wv fp32 -> fp16 (once).  65536 elems = 32768 half2.
// ============================================================================
__global__ void wconv_kernel(const float* __restrict__ Wv)
{
    int i = blockIdx.x * 256 + threadIdx.x;       // 128 blocks
    float2 v = ((const float2*)Wv)[i];
    g_wh[i] = __floats2half2_rn(v.x, v.y);
}

// ============================================================================
// K0b: qproj — warp per output.  grid (32 a-chunks, 32 b), 256 thr.
// ============================================================================
__global__ void qproj_kernel(const float* __restrict__ query,
                             const float* __restrict__ Wq,
                             const float* __restrict__ bq,
                             const float* __restrict__ bv)
{
    int b = blockIdx.y, tid = threadIdx.x;
    int warp = tid >> 5, lane = tid & 31;
    __shared__ float q_sm[AD];
    q_sm[tid] = query[b * AD + tid];
    __syncthreads();
    int a = blockIdx.x * 8 + warp;
    const float* wrow = Wq + (size_t)a * AD;
    float acc = 0.f;
#pragma unroll
    for (int i = 0; i < 8; i++) acc += q_sm[lane + 32 * i] * wrow[lane + 32 * i];
#pragma unroll
    for (int o = 16; o > 0; o >>= 1) acc += __shfl_xor_sync(0xffffffff, acc, o);
    if (lane == 0) g_s[b * AD + a] = acc + bq[a] + bv[a];
}

// ============================================================================
// K1: per (b, 128-row T-tile): keys GEMM (fp16 mma.sync m16n8k16, fp32 acc)
// -> tanh score -> tile softmax -> partial context.
// 512 threads = 16 warps in 4(m)x4(n); each warp owns 32x64 of C.
// ============================================================================
__global__ void __launch_bounds__(512, 1)
attn_main(const float* __restrict__ values,
          const float* __restrict__ wscore)
{
    extern __shared__ __align__(16) char dsm[];
    const int tid  = threadIdx.x;
    const int lane = tid & 31, warp = tid >> 5;
    const int wm = warp >> 2, wn = warp & 3;
    const int tile = blockIdx.x, b = blockIdx.y;
    const int t0 = tile * TILE_T;

    __shared__ float s_sm[AD], w_sm[AD];
    __shared__ float e_sm[TILE_T], p_sm[TILE_T];
    __shared__ float redm[4], redl[4];
    __shared__ float m_sh;

    if (tid < AD) { s_sm[tid] = g_s[b * AD + tid]; w_sm[tid] = wscore[tid]; }
    if (tid < TILE_T) e_sm[tid] = 0.f;

    const float* vbase = values + ((size_t)b * T_LEN + t0) * VD;
    uint32_t sbase = (uint32_t)__cvta_generic_to_shared(dsm);

    float acc[2][8][4];
#pragma unroll
    for (int i = 0; i < 2; i++)
#pragma unroll
        for (int j = 0; j < 8; j++)
#pragma unroll
            for (int k = 0; k < 4; k++) acc[i][j][k] = 0.f;

    auto load_tiles = [&](int stage, int kc) {
        // A (values) fp32: 128 rows x 32 floats = 1024 x 16B
#pragma unroll
        for (int r = 0; r < 2; r++) {
            int idx = tid + r * 512;
            int row = idx >> 3, seg = idx & 7;
            cp16(sbase + stage * AF32_STAGE + row * AF32_STRIDE + seg * 16,
                 vbase + (size_t)row * VD + kc * KC + seg * 4);
        }
        // B (Wv fp16): 256 rows x 32 halves = 1024 x 16B
#pragma unroll
        for (int r = 0; r < 2; r++) {
            int idx = tid + r * 512;
            int row = idx >> 2, seg = idx & 3;
            cp16(sbase + OFF_B2 + stage * B2_STAGE + row * (B2_STRIDE_H2 * 4) + seg * 16,
                 (const char*)g_wh + (size_t)row * (VD * 2) + kc * (KC * 2) + seg * 16);
        }
    };

    load_tiles(0, 0);
    cp_commit();

    const int kq = lane & 3;
    const int rbase0 = wm * 32 + (lane >> 2);
    const int crow = tid >> 2, cseg = tid & 3;    // conversion assignment

    for (int kc = 0; kc < NKC; kc++) {
        if (kc + 1 < NKC) {
            load_tiles((kc + 1) & 1, kc + 1);
            cp_commit();
            cp_wait<1>();
        } else {
            cp_wait<0>();
        }
        __syncthreads();   // stage kc loads visible

        // convert A fp32 -> fp16 (each thread: 8 floats of one row segment)
        {
            const float4* src = (const float4*)(dsm + (kc & 1) * AF32_STAGE
                                                + crow * AF32_STRIDE + cseg * 32);
            float4 v0 = src[0], v1 = src[1];
            __half2* dst = (__half2*)(dsm + OFF_A2) + crow * A2_STRIDE_H2 + cseg * 4;
            dst[0] = __floats2half2_rn(v0.x, v0.y);
            dst[1] = __floats2half2_rn(v0.z, v0.w);
            dst[2] = __floats2half2_rn(v1.x, v1.y);
            dst[3] = __floats2half2_rn(v1.z, v1.w);
        }
        __syncthreads();   // A2 ready

        const uint32_t* A2 = (const uint32_t*)(dsm + OFF_A2);
        const uint32_t* B2 = (const uint32_t*)(dsm + OFF_B2 + (kc & 1) * B2_STAGE);
#pragma unroll
        for (int ks = 0; ks < 2; ks++) {
            uint32_t af[2][4];
#pragma unroll
            for (int i = 0; i < 2; i++) {
                int r0 = rbase0 + i * 16;
                af[i][0] = A2[r0 * A2_STRIDE_H2 + ks * 8 + kq];
                af[i][1] = A2[(r0 + 8) * A2_STRIDE_H2 + ks * 8 + kq];
                af[i][2] = A2[r0 * A2_STRIDE_H2 + ks * 8 + kq + 4];
                af[i][3] = A2[(r0 + 8) * A2_STRIDE_H2 + ks * 8 + kq + 4];
            }
#pragma unroll
            for (int j = 0; j < 8; j++) {
                int n = wn * 64 + j * 8 + (lane >> 2);
                uint32_t b0 = B2[n * B2_STRIDE_H2 + ks * 8 + kq];
                uint32_t b1 = B2[n * B2_STRIDE_H2 + ks * 8 + kq + 4];
#pragma unroll
                for (int i = 0; i < 2; i++)
                    mma_f16(acc[i][j][0], acc[i][j][1], acc[i][j][2], acc[i][j][3],
                            af[i][0], af[i][1], af[i][2], af[i][3], b0, b1);
            }
        }
        __syncthreads();   // mma done before next-iter load overwrites stage
    }

    // ---- score epilogue: e[t] = sum_a w[a]*tanh(keys[t,a] + s[a]) ----
#pragma unroll
    for (int i = 0; i < 2; i++) {
        float sA = 0.f, sB = 0.f;
#pragma unroll
        for (int j = 0; j < 8; j++) {
            int c0 = wn * 64 + j * 8 + 2 * (lane & 3);
            int c1 = c0 + 1;
            sA += w_sm[c0] * tanhf(acc[i][j][0] + s_sm[c0])
                + w_sm[c1] * tanhf(acc[i][j][1] + s_sm[c1]);
            sB += w_sm[c0] * tanhf(acc[i][j][2] + s_sm[c0])
                + w_sm[c1] * tanhf(acc[i][j][3] + s_sm[c1]);
        }
        sA += __shfl_xor_sync(0xffffffff, sA, 1);
        sA += __shfl_xor_sync(0xffffffff, sA, 2);
        sB += __shfl_xor_sync(0xffffffff, sB, 1);
        sB += __shfl_xor_sync(0xffffffff, sB, 2);
        if ((lane & 3) == 0) {
            int r0 = wm * 32 + i * 16 + (lane >> 2);
            atomicAdd(&e_sm[r0], sA);
            atomicAdd(&e_sm[r0 + 8], sB);
        }
    }
    __syncthreads();

    // ---- tile-local softmax stats ----
    if (tid < TILE_T) {
        float v = e_sm[tid];
#pragma unroll
        for (int o = 16; o > 0; o >>= 1) v = fmaxf(v, __shfl_xor_sync(0xffffffff, v, o));
        if (lane == 0) redm[warp] = v;
    }
    __syncthreads();
    if (tid == 0)
        m_sh = fmaxf(fmaxf(redm[0], redm[1]), fmaxf(redm[2], redm[3]));
    __syncthreads();
    float mt = m_sh;
    if (tid < TILE_T) {
        float e = e_sm[tid];
        float p = __expf(e - mt);
        p_sm[tid] = p;
        g_e[b * T_LEN + t0 + tid] = e;
#pragma unroll
        for (int o = 16; o > 0; o >>= 1) p += __shfl_xor_sync(0xffffffff, p, o);
        if (lane == 0) redl[warp] = p;
    }
    __syncthreads();
    if (tid == 0) {
        g_m[b * NTILE + tile] = mt;
        g_l[b * NTILE + tile] = redl[0] + redl[1] + redl[2] + redl[3];
    }
    __syncthreads();   // p_sm visible; GEMM smem free for reuse

    // ---- partial context: cp[v] = sum_t p[t]*values[b,t0+t,v] (L2 re-read) ----
    {
        int v = tid & 255, half = tid >> 8;
        const float* vp = values + ((size_t)b * T_LEN + t0 + half * 64) * VD + v;
        float ca = 0.f;
#pragma unroll 8
        for (int t = 0; t < 64; t++) ca += p_sm[half * 64 + t] * vp[(size_t)t * VD];
        float* cacc = (float*)dsm;
        cacc[half * 256 + v] = ca;
        __syncthreads();
        if (tid < VD)
            g_cp[((b * NTILE + tile) << 8) + tid] = cacc[tid] + cacc[256 + tid];
    }
}

// ============================================================================
// K2: per-b combine: global softmax + final a and c.
// out layout: c [B,VD] then a [B,T]   (bv_score dropped: softmax-invariant)
// ============================================================================
__global__ void combine_kernel(float* __restrict__ out)
{
    int b = blockIdx.x, tid = threadIdx.x;
    __shared__ float mt[NTILE], lt[NTILE];
    __shared__ float M_sh, invL_sh;
    if (tid < NTILE) { mt[tid] = g_m[b * NTILE + tid]; lt[tid] = g_l[b * NTILE + tid]; }
    __syncthreads();
    if (tid == 0) {
        float M = -1e30f;
        for (int i = 0; i < NTILE; i++) M = fmaxf(M, mt[i]);
        float L = 0.f;
        for (int i = 0; i < NTILE; i++) L += lt[i] * __expf(mt[i] - M);
        M_sh = M;
        invL_sh = 1.0f / L;
    }
    __syncthreads();
    float M = M_sh, invL = invL_sh;
    float* c_out = out;
    float* a_out = out + BATCH * VD;
    for (int t = tid; t < T_LEN; t += blockDim.x)
        a_out[b * T_LEN + t] = __expf(g_e[b * T_LEN + t] - M) * invL;
    if (tid < VD) {
        float acc = 0.f;
        for (int i = 0; i < NTILE; i++)
            acc += g_cp[((b * NTILE + i) << 8) + tid] * __expf(mt[i] - M);
        c_out[b * VD + tid] = acc * invL;
    }
}

// ============================================================================
// launch
// ============================================================================
extern "C" void kernel_launch(void* const* d_in, const int* in_sizes, int n_in,
                              void* d_out, int out_size)
{
    const float* query  = (const float*)d_in[0];
    const float* values = (const float*)d_in[1];
    const float* Wq     = (const float*)d_in[2];
    const float* bq     = (const float*)d_in[3];
    const float* Wv     = (const float*)d_in[4];
    const float* bv     = (const float*)d_in[5];
    const float* wsc    = (const float*)d_in[6];
    // d_in[7] = bv_score: additive constant inside softmax -> no effect
    (void)in_sizes; (void)n_in; (void)out_size;
    float* out = (float*)d_out;

    cudaFuncSetAttribute(attn_main, cudaFuncAttributeMaxDynamicSharedMemorySize, DSMEM_BYTES);

    wconv_kernel<<<128, 256>>>(Wv);
    qproj_kernel<<<dim3(32, BATCH), 256>>>(query, Wq, bq, bv);
    attn_main<<<dim3(NTILE, BATCH), 512, DSMEM_BYTES>>>(values, wsc);
    combine_kernel<<<BATCH, 256>>>(out);
}

// round 7
// speedup vs baseline: 1.6698x; 1.2004x over previous
#include <cuda_runtime.h>
#include <cuda_fp16.h>
#include <cstdint>

#define T_LEN  4096
#define BATCH  32
#define AD     256
#define VD     256
#define TILE_T 128
#define NTILE  (T_LEN / TILE_T)   // 32
#define KC     32                 // K floats per pipeline chunk
#define NKC    (VD / KC)          // 8

// ---- smem layout (bytes), fp16 tiles, 80B padded rows (32 halves + 16B pad)
#define ROW_B   80
#define A_TILE  (TILE_T * ROW_B)          // 10240
#define B_TILE  (AD * ROW_B)              // 20480
#define OFF_B   (2 * A_TILE)              // 20480
#define DSMEM_BYTES (OFF_B + 2 * B_TILE)  // 61440

// ---- device scratch ----
__device__ float   g_s[BATCH * AD];
__device__ float   g_e[BATCH * T_LEN];
__device__ float   g_m[BATCH * NTILE];
__device__ float   g_l[BATCH * NTILE];
__device__ float   g_cp[BATCH * NTILE * VD];
__device__ __half2 g_wh[AD * VD / 2];     // Wv fp16, row-major [a][k]

// ---- helpers ----
__device__ __forceinline__ void cp16(uint32_t dst, const void* src) {
    asm volatile("cp.async.cg.shared.global [%0], [%1], 16;" :: "r"(dst), "l"(src));
}
__device__ __forceinline__ void cp_commit() { asm volatile("cp.async.commit_group;"); }
template <int N> __device__ __forceinline__ void cp_wait() {
    asm volatile("cp.async.wait_group %0;" :: "n"(N));
}
__device__ __forceinline__ void ldsm_x4(uint32_t& r0, uint32_t& r1, uint32_t& r2,
                                        uint32_t& r3, uint32_t addr) {
    asm volatile("ldmatrix.sync.aligned.m8n8.x4.shared.b16 {%0,%1,%2,%3}, [%4];"
                 : "=r"(r0), "=r"(r1), "=r"(r2), "=r"(r3) : "r"(addr));
}
__device__ __forceinline__ void mma_f16(
    float& d0, float& d1, float& d2, float& d3,
    uint32_t a0, uint32_t a1, uint32_t a2, uint32_t a3,
    uint32_t b0, uint32_t b1)
{
    asm volatile(
        "mma.sync.aligned.m16n8k16.row.col.f32.f16.f16.f32 "
        "{%0,%1,%2,%3}, {%4,%5,%6,%7}, {%8,%9}, {%0,%1,%2,%3};"
        : "+f"(d0), "+f"(d1), "+f"(d2), "+f"(d3)
        : "r"(a0), "r"(a1), "r"(a2), "r"(a3), "r"(b0), "r"(b1));
}
__device__ __forceinline__ float tanha(float x) {
    float y;
    asm("tanh.approx.f32 %0, %1;" : "=f"(y) : "f"(x));
    return y;
}

// ============================================================================
// K0a: Wv fp32 -> fp16 (once).
// ============================================================================
__global__ void wconv_kernel(const float* __restrict__ Wv)
{
    int i = blockIdx.x * 256 + threadIdx.x;       // 128 blocks
    float2 v = ((const float2*)Wv)[i];
    g_wh[i] = __floats2half2_rn(v.x, v.y);
}

// ============================================================================
// K0b: qproj — warp per output.
// ============================================================================
__global__ void qproj_kernel(const float* __restrict__ query,
                             const float* __restrict__ Wq,
                             const float* __restrict__ bq,
                             const float* __restrict__ bv)
{
    int b = blockIdx.y, tid = threadIdx.x;
    int warp = tid >> 5, lane = tid & 31;
    __shared__ float q_sm[AD];
    q_sm[tid] = query[b * AD + tid];
    __syncthreads();
    int a = blockIdx.x * 8 + warp;
    const float* wrow = Wq + (size_t)a * AD;
    float acc = 0.f;
#pragma unroll
    for (int i = 0; i < 8; i++) acc += q_sm[lane + 32 * i] * wrow[lane + 32 * i];
#pragma unroll
    for (int o = 16; o > 0; o >>= 1) acc += __shfl_xor_sync(0xffffffff, acc, o);
    if (lane == 0) g_s[b * AD + a] = acc + bq[a] + bv[a];
}

// ============================================================================
// K1: per (b, 128-row T-tile). 256 threads = 8 warps in 2(m)x4(n) grid,
// each warp owns 64x64 of C. fp16 mma m16n8k16, ldmatrix fragment loads,
// A converted fp32->fp16 through registers, 1 barrier per K-chunk.
// ============================================================================
__global__ void __launch_bounds__(256, 1)
attn_main(const float* __restrict__ values,
          const float* __restrict__ wscore)
{
    extern __shared__ __align__(16) char dsm[];
    const int tid  = threadIdx.x;
    const int lane = tid & 31, warp = tid >> 5;
    const int wm = warp >> 2, wn = warp & 3;    // 2 x 4
    const int tile = blockIdx.x, b = blockIdx.y;
    const int t0 = tile * TILE_T;

    __shared__ float s_sm[AD], w_sm[AD];
    __shared__ float e_sm[TILE_T], p_sm[TILE_T];
    __shared__ float redm[4], redl[4];
    __shared__ float m_sh;

    s_sm[tid] = g_s[b * AD + tid];
    w_sm[tid] = wscore[tid];
    if (tid < TILE_T) e_sm[tid] = 0.f;

    const float* vbase = values + ((size_t)b * T_LEN + t0) * VD;
    const uint32_t sbase = (uint32_t)__cvta_generic_to_shared(dsm);

    float acc[4][8][4];
#pragma unroll
    for (int i = 0; i < 4; i++)
#pragma unroll
        for (int j = 0; j < 8; j++)
#pragma unroll
            for (int k = 0; k < 4; k++) acc[i][j][k] = 0.f;

    // producer thread mapping (4 segments each for A and B)
    // A: 1024 float4 segs: row = idx>>3 (0..127), seg = idx&7
    // B: 1024 16B segs:    row = idx>>2 (0..255), seg = idx&3
    float4 av[4];

    auto ldgA = [&](int kc) {
#pragma unroll
        for (int r = 0; r < 4; r++) {
            int idx = tid + r * 256;
            int row = idx >> 3, seg = idx & 7;
            av[r] = __ldg((const float4*)(vbase + (size_t)row * VD + kc * KC) + seg);
        }
    };
    auto cpB = [&](int buf, int kc) {
#pragma unroll
        for (int r = 0; r < 4; r++) {
            int idx = tid + r * 256;
            int row = idx >> 2, seg = idx & 3;
            cp16(sbase + OFF_B + buf * B_TILE + row * ROW_B + seg * 16,
                 (const char*)g_wh + (size_t)row * (VD * 2) + kc * (KC * 2) + seg * 16);
        }
    };
    auto stsA = [&](int buf) {
#pragma unroll
        for (int r = 0; r < 4; r++) {
            int idx = tid + r * 256;
            int row = idx >> 3, seg = idx & 7;
            __half2 h0 = __floats2half2_rn(av[r].x, av[r].y);
            __half2 h1 = __floats2half2_rn(av[r].z, av[r].w);
            uint2 u = make_uint2(*(uint32_t*)&h0, *(uint32_t*)&h1);
            *(uint2*)(dsm + buf * A_TILE + row * ROW_B + seg * 8) = u;
        }
    };

    // ldmatrix lane address components
    const int aRowLane = (lane & 7) | (((lane >> 3) & 1) << 3);   // 0..15
    const int aColOff  = ((lane >> 4) & 1) * 16;
    const int aBaseRow = wm * 64 + aRowLane;
    const int bNLane   = ((lane >> 4) & 1) * 8 + (lane & 7);
    const int bColOff  = ((lane >> 3) & 1) * 16;
    const int bBaseRow = wn * 64 + bNLane;

    // prologue: chunk 0
    ldgA(0);
    cpB(0, 0);
    cp_commit();
    stsA(0);
    cp_wait<0>();
    __syncthreads();

    for (int kc = 0; kc < NKC; kc++) {
        if (kc + 1 < NKC) {
            ldgA(kc + 1);
            cpB((kc + 1) & 1, kc + 1);
            cp_commit();
        }
        // ---- mma on buffers kc&1 ----
        {
            uint32_t abuf = sbase + (kc & 1) * A_TILE;
            uint32_t bbuf = sbase + OFF_B + (kc & 1) * B_TILE;
#pragma unroll
            for (int ks = 0; ks < 2; ks++) {
                uint32_t af[4][4];
#pragma unroll
                for (int i = 0; i < 4; i++)
                    ldsm_x4(af[i][0], af[i][1], af[i][2], af[i][3],
                            abuf + (aBaseRow + i * 16) * ROW_B + ks * 32 + aColOff);
#pragma unroll
                for (int jp = 0; jp < 4; jp++) {
                    uint32_t b0a, b1a, b0b, b1b;
                    ldsm_x4(b0a, b1a, b0b, b1b,
                            bbuf + (bBaseRow + jp * 16) * ROW_B + ks * 32 + bColOff);
#pragma unroll
                    for (int i = 0; i < 4; i++) {
                        mma_f16(acc[i][2*jp][0], acc[i][2*jp][1], acc[i][2*jp][2], acc[i][2*jp][3],
                                af[i][0], af[i][1], af[i][2], af[i][3], b0a, b1a);
                        mma_f16(acc[i][2*jp+1][0], acc[i][2*jp+1][1], acc[i][2*jp+1][2], acc[i][2*jp+1][3],
                                af[i][0], af[i][1], af[i][2], af[i][3], b0b, b1b);
                    }
                }
            }
        }
        if (kc + 1 < NKC) {
            stsA((kc + 1) & 1);
            cp_wait<0>();
            __syncthreads();
        }
    }

    // ---- score epilogue: e[t] = sum_a w[a]*tanh(keys[t,a] + s[a]) ----
#pragma unroll
    for (int i = 0; i < 4; i++) {
        float sA = 0.f, sB = 0.f;
#pragma unroll
        for (int j = 0; j < 8; j++) {
            int c0 = wn * 64 + j * 8 + 2 * (lane & 3);
            int c1 = c0 + 1;
            sA += w_sm[c0] * tanha(acc[i][j][0] + s_sm[c0])
                + w_sm[c1] * tanha(acc[i][j][1] + s_sm[c1]);
            sB += w_sm[c0] * tanha(acc[i][j][2] + s_sm[c0])
                + w_sm[c1] * tanha(acc[i][j][3] + s_sm[c1]);
        }
        sA += __shfl_xor_sync(0xffffffff, sA, 1);
        sA += __shfl_xor_sync(0xffffffff, sA, 2);
        sB += __shfl_xor_sync(0xffffffff, sB, 1);
        sB += __shfl_xor_sync(0xffffffff, sB, 2);
        if ((lane & 3) == 0) {
            int r0 = wm * 64 + i * 16 + (lane >> 2);
            atomicAdd(&e_sm[r0], sA);
            atomicAdd(&e_sm[r0 + 8], sB);
        }
    }
    __syncthreads();

    // ---- tile-local softmax stats (warps 0-3 cover 128 rows) ----
    if (tid < TILE_T) {
        float v = e_sm[tid];
#pragma unroll
        for (int o = 16; o > 0; o >>= 1) v = fmaxf(v, __shfl_xor_sync(0xffffffff, v, o));
        if (lane == 0) redm[warp] = v;
    }
    __syncthreads();
    if (tid == 0)
        m_sh = fmaxf(fmaxf(redm[0], redm[1]), fmaxf(redm[2], redm[3]));
    __syncthreads();
    float mt = m_sh;
    if (tid < TILE_T) {
        float e = e_sm[tid];
        float p = __expf(e - mt);
        p_sm[tid] = p;
        g_e[b * T_LEN + t0 + tid] = e;
#pragma unroll
        for (int o = 16; o > 0; o >>= 1) p += __shfl_xor_sync(0xffffffff, p, o);
        if (lane == 0) redl[warp] = p;
    }
    __syncthreads();
    if (tid == 0) {
        g_m[b * NTILE + tile] = mt;
        g_l[b * NTILE + tile] = redl[0] + redl[1] + redl[2] + redl[3];
    }
    __syncthreads();

    // ---- partial context: cp[v] = sum_t p[t]*values[b,t0+t,v] (L2 re-read) ----
    {
        const float* vp = vbase + tid;
        float ca = 0.f;
#pragma unroll 8
        for (int t = 0; t < TILE_T; t++) ca += p_sm[t] * vp[(size_t)t * VD];
        g_cp[((b * NTILE + tile) << 8) + tid] = ca;
    }
}

// ============================================================================
// K2: combine — grid (8 chunks, B). chunk 0 also emits c.
// out layout: c [B,VD] then a [B,T]   (bv_score dropped: softmax-invariant)
// ============================================================================
__global__ void combine_kernel(float* __restrict__ out)
{
    int chunk = blockIdx.x, b = blockIdx.y, tid = threadIdx.x;
    __shared__ float mt[NTILE], lt[NTILE];
    __shared__ float M_sh, invL_sh;
    if (tid < NTILE) { mt[tid] = g_m[b * NTILE + tid]; lt[tid] = g_l[b * NTILE + tid]; }
    __syncthreads();
    if (tid == 0) {
        float M = -1e30f;
#pragma unroll
        for (int i = 0; i < NTILE; i++) M = fmaxf(M, mt[i]);
        float L = 0.f;
#pragma unroll
        for (int i = 0; i < NTILE; i++) L += lt[i] * __expf(mt[i] - M);
        M_sh = M;
        invL_sh = 1.0f / L;
    }
    __syncthreads();
    float M = M_sh, invL = invL_sh;
    float* a_out = out + BATCH * VD;
    int t = chunk * 512 + tid;
    a_out[b * T_LEN + t]       = __expf(g_e[b * T_LEN + t] - M) * invL;
    a_out[b * T_LEN + t + 256] = __expf(g_e[b * T_LEN + t + 256] - M) * invL;
    if (chunk == 0) {
        float acc = 0.f;
#pragma unroll
        for (int i = 0; i < NTILE; i++)
            acc += g_cp[((b * NTILE + i) << 8) + tid] * __expf(mt[i] - M);
        out[b * VD + tid] = acc * invL;
    }
}

// ============================================================================
// launch
// ============================================================================
extern "C" void kernel_launch(void* const* d_in, const int* in_sizes, int n_in,
                              void* d_out, int out_size)
{
    const float* query  = (const float*)d_in[0];
    const float* values = (const float*)d_in[1];
    const float* Wq     = (const float*)d_in[2];
    const float* bq     = (const float*)d_in[3];
    const float* Wv     = (const float*)d_in[4];
    const float* bv     = (const float*)d_in[5];
    const float* wsc    = (const float*)d_in[6];
    // d_in[7] = bv_score: additive constant inside softmax -> no effect
    (void)in_sizes; (void)n_in; (void)out_size;
    float* out = (float*)d_out;

    cudaFuncSetAttribute(attn_main, cudaFuncAttributeMaxDynamicSharedMemorySize, DSMEM_BYTES);

    wconv_kernel<<<128, 256>>>(Wv);
    qproj_kernel<<<dim3(32, BATCH), 256>>>(query, Wq, bq, bv);
    attn_main<<<dim3(NTILE, BATCH), 256, DSMEM_BYTES>>>(values, wsc);
    combine_kernel<<<dim3(8, BATCH), 256>>>(out);
}

// round 9
// speedup vs baseline: 1.8884x; 1.1309x over previous
#include <cuda_runtime.h>
#include <cuda_fp16.h>
#include <cstdint>

#define T_LEN  4096
#define BATCH  32
#define AD     256
#define VD     256
#define TILE_T 128
#define NTILE  (T_LEN / TILE_T)   // 32
#define KC     32                 // K floats per pipeline chunk
#define NKC    (VD / KC)          // 8

// ---- smem layout (bytes), fp16 tiles, 80B padded rows (32 halves + 16B pad)
#define ROW_B   80
#define A_TILE  (TILE_T * ROW_B)          // 10240
#define B_TILE  (AD * ROW_B)              // 20480
#define OFF_B   (2 * A_TILE)              // 20480
#define DSMEM_BYTES (OFF_B + 2 * B_TILE)  // 61440

// ---- device scratch ----
__device__ float   g_s[BATCH * AD];
__device__ float   g_e[BATCH * T_LEN];
__device__ float   g_m[BATCH * NTILE];
__device__ float   g_l[BATCH * NTILE];
__device__ float   g_cp[BATCH * NTILE * VD];
__device__ float   g_M[BATCH];
__device__ float   g_invL[BATCH];
__device__ __half2 g_wh[AD * VD / 2];     // Wv fp16, row-major [a][k]

// ---- helpers ----
__device__ __forceinline__ void cp16(uint32_t dst, const void* src) {
    asm volatile("cp.async.cg.shared.global [%0], [%1], 16;" :: "r"(dst), "l"(src));
}
__device__ __forceinline__ void cp_commit() { asm volatile("cp.async.commit_group;"); }
template <int N> __device__ __forceinline__ void cp_wait() {
    asm volatile("cp.async.wait_group %0;" :: "n"(N));
}
__device__ __forceinline__ void ldsm_x4(uint32_t& r0, uint32_t& r1, uint32_t& r2,
                                        uint32_t& r3, uint32_t addr) {
    asm volatile("ldmatrix.sync.aligned.m8n8.x4.shared.b16 {%0,%1,%2,%3}, [%4];"
                 : "=r"(r0), "=r"(r1), "=r"(r2), "=r"(r3) : "r"(addr));
}
__device__ __forceinline__ void mma_f16(
    float& d0, float& d1, float& d2, float& d3,
    uint32_t a0, uint32_t a1, uint32_t a2, uint32_t a3,
    uint32_t b0, uint32_t b1)
{
    asm volatile(
        "mma.sync.aligned.m16n8k16.row.col.f32.f16.f16.f32 "
        "{%0,%1,%2,%3}, {%4,%5,%6,%7}, {%8,%9}, {%0,%1,%2,%3};"
        : "+f"(d0), "+f"(d1), "+f"(d2), "+f"(d3)
        : "r"(a0), "r"(a1), "r"(a2), "r"(a3), "r"(b0), "r"(b1));
}
__device__ __forceinline__ float tanha(float x) {
    float y;
    asm("tanh.approx.f32 %0, %1;" : "=f"(y) : "f"(x));
    return y;
}

// ============================================================================
// K0a: Wv fp32 -> fp16 (once).
// ============================================================================
__global__ void wconv_kernel(const float* __restrict__ Wv)
{
    int i = blockIdx.x * 256 + threadIdx.x;       // 128 blocks
    float2 v = ((const float2*)Wv)[i];
    g_wh[i] = __floats2half2_rn(v.x, v.y);
}

// ============================================================================
// K0b: qproj — warp per output.
// ============================================================================
__global__ void qproj_kernel(const float* __restrict__ query,
                             const float* __restrict__ Wq,
                             const float* __restrict__ bq,
                             const float* __restrict__ bv)
{
    int b = blockIdx.y, tid = threadIdx.x;
    int warp = tid >> 5, lane = tid & 31;
    __shared__ float q_sm[AD];
    q_sm[tid] = query[b * AD + tid];
    __syncthreads();
    int a = blockIdx.x * 8 + warp;
    const float* wrow = Wq + (size_t)a * AD;
    float acc = 0.f;
#pragma unroll
    for (int i = 0; i < 8; i++) acc += q_sm[lane + 32 * i] * wrow[lane + 32 * i];
#pragma unroll
    for (int o = 16; o > 0; o >>= 1) acc += __shfl_xor_sync(0xffffffff, acc, o);
    if (lane == 0) g_s[b * AD + a] = acc + bq[a] + bv[a];
}

// ============================================================================
// K1: per (b, 128-row T-tile). 512 threads = 16 warps in 4(m)x4(n) grid,
// each warp owns 32x64 of C (4 warps/SMSP for HMMA pipe fill).
// fp16 mma m16n8k16, ldmatrix feeds, A cvt fp32->fp16 via registers.
// ============================================================================
__global__ void __launch_bounds__(512, 1)
attn_main(const float* __restrict__ values,
          const float* __restrict__ wscore)
{
    extern __shared__ __align__(16) char dsm[];
    const int tid  = threadIdx.x;
    const int lane = tid & 31, warp = tid >> 5;
    const int wm = warp >> 2, wn = warp & 3;    // 4 x 4
    const int tile = blockIdx.x, b = blockIdx.y;
    const int t0 = tile * TILE_T;

    __shared__ float s_sm[AD], w_sm[AD];
    __shared__ float e_sm[TILE_T], p_sm[TILE_T];
    __shared__ float redm[4], redl[4];
    __shared__ float m_sh;

    if (tid < AD) { s_sm[tid] = g_s[b * AD + tid]; w_sm[tid] = wscore[tid]; }
    if (tid < TILE_T) e_sm[tid] = 0.f;

    const float* vbase = values + ((size_t)b * T_LEN + t0) * VD;
    const uint32_t sbase = (uint32_t)__cvta_generic_to_shared(dsm);

    float acc[2][8][4];
#pragma unroll
    for (int i = 0; i < 2; i++)
#pragma unroll
        for (int j = 0; j < 8; j++)
#pragma unroll
            for (int k = 0; k < 4; k++) acc[i][j][k] = 0.f;

    // producers: A 1024 float4 segs (2/thread), B 1024 16B segs (2/thread)
    float4 av[2];
    auto ldgA = [&](int kc) {
#pragma unroll
        for (int r = 0; r < 2; r++) {
            int idx = tid + r * 512;
            int row = idx >> 3, seg = idx & 7;
            av[r] = __ldg((const float4*)(vbase + (size_t)row * VD + kc * KC) + seg);
        }
    };
    auto cpB = [&](int buf, int kc) {
#pragma unroll
        for (int r = 0; r < 2; r++) {
            int idx = tid + r * 512;
            int row = idx >> 2, seg = idx & 3;
            cp16(sbase + OFF_B + buf * B_TILE + row * ROW_B + seg * 16,
                 (const char*)g_wh + (size_t)row * (VD * 2) + kc * (KC * 2) + seg * 16);
        }
    };
    auto stsA = [&](int buf) {
#pragma unroll
        for (int r = 0; r < 2; r++) {
            int idx = tid + r * 512;
            int row = idx >> 3, seg = idx & 7;
            __half2 h0 = __floats2half2_rn(av[r].x, av[r].y);
            __half2 h1 = __floats2half2_rn(av[r].z, av[r].w);
            uint2 u = make_uint2(*(uint32_t*)&h0, *(uint32_t*)&h1);
            *(uint2*)(dsm + buf * A_TILE + row * ROW_B + seg * 8) = u;
        }
    };

    // ldmatrix lane address components
    const int aRowLane = (lane & 7) | (((lane >> 3) & 1) << 3);   // 0..15
    const int aColOff  = ((lane >> 4) & 1) * 16;
    const int aBaseRow = wm * 32 + aRowLane;
    const int bNLane   = ((lane >> 4) & 1) * 8 + (lane & 7);
    const int bColOff  = ((lane >> 3) & 1) * 16;
    const int bBaseRow = wn * 64 + bNLane;

    // prologue: chunk 0
    ldgA(0);
    cpB(0, 0);
    cp_commit();
    stsA(0);
    cp_wait<0>();
    __syncthreads();

    for (int kc = 0; kc < NKC; kc++) {
        if (kc + 1 < NKC) {
            ldgA(kc + 1);
            cpB((kc + 1) & 1, kc + 1);
            cp_commit();
        }
        // ---- mma on buffers kc&1 ----
        {
            uint32_t abuf = sbase + (kc & 1) * A_TILE;
            uint32_t bbuf = sbase + OFF_B + (kc & 1) * B_TILE;
#pragma unroll
            for (int ks = 0; ks < 2; ks++) {
                uint32_t af[2][4];
#pragma unroll
                for (int i = 0; i < 2; i++)
                    ldsm_x4(af[i][0], af[i][1], af[i][2], af[i][3],
                            abuf + (aBaseRow + i * 16) * ROW_B + ks * 32 + aColOff);
#pragma unroll
                for (int jp = 0; jp < 4; jp++) {
                    uint32_t b0a, b1a, b0b, b1b;
                    ldsm_x4(b0a, b1a, b0b, b1b,
                            bbuf + (bBaseRow + jp * 16) * ROW_B + ks * 32 + bColOff);
#pragma unroll
                    for (int i = 0; i < 2; i++) {
                        mma_f16(acc[i][2*jp][0], acc[i][2*jp][1], acc[i][2*jp][2], acc[i][2*jp][3],
                                af[i][0], af[i][1], af[i][2], af[i][3], b0a, b1a);
                        mma_f16(acc[i][2*jp+1][0], acc[i][2*jp+1][1], acc[i][2*jp+1][2], acc[i][2*jp+1][3],
                                af[i][0], af[i][1], af[i][2], af[i][3], b0b, b1b);
                    }
                }
            }
        }
        if (kc + 1 < NKC) {
            stsA((kc + 1) & 1);
            cp_wait<0>();
            __syncthreads();
        }
    }

    // ---- score epilogue: e[t] = sum_a w[a]*tanh(keys[t,a] + s[a]) ----
#pragma unroll
    for (int i = 0; i < 2; i++) {
        float sA = 0.f, sB = 0.f;
#pragma unroll
        for (int j = 0; j < 8; j++) {
            int c0 = wn * 64 + j * 8 + 2 * (lane & 3);
            int c1 = c0 + 1;
            sA += w_sm[c0] * tanha(acc[i][j][0] + s_sm[c0])
                + w_sm[c1] * tanha(acc[i][j][1] + s_sm[c1]);
            sB += w_sm[c0] * tanha(acc[i][j][2] + s_sm[c0])
                + w_sm[c1] * tanha(acc[i][j][3] + s_sm[c1]);
        }
        sA += __shfl_xor_sync(0xffffffff, sA, 1);
        sA += __shfl_xor_sync(0xffffffff, sA, 2);
        sB += __shfl_xor_sync(0xffffffff, sB, 1);
        sB += __shfl_xor_sync(0xffffffff, sB, 2);
        if ((lane & 3) == 0) {
            int r0 = wm * 32 + i * 16 + (lane >> 2);
            atomicAdd(&e_sm[r0], sA);
            atomicAdd(&e_sm[r0 + 8], sB);
        }
    }
    __syncthreads();

    // ---- tile-local softmax stats (warps 0-3 cover 128 rows) ----
    if (tid < TILE_T) {
        float v = e_sm[tid];
#pragma unroll
        for (int o = 16; o > 0; o >>= 1) v = fmaxf(v, __shfl_xor_sync(0xffffffff, v, o));
        if (lane == 0) redm[warp] = v;
    }
    __syncthreads();
    if (tid == 0)
        m_sh = fmaxf(fmaxf(redm[0], redm[1]), fmaxf(redm[2], redm[3]));
    __syncthreads();
    float mt = m_sh;
    if (tid < TILE_T) {
        float e = e_sm[tid];
        float p = __expf(e - mt);
        p_sm[tid] = p;
        g_e[b * T_LEN + t0 + tid] = e;
#pragma unroll
        for (int o = 16; o > 0; o >>= 1) p += __shfl_xor_sync(0xffffffff, p, o);
        if (lane == 0) redl[warp] = p;
    }
    __syncthreads();
    if (tid == 0) {
        g_m[b * NTILE + tile] = mt;
        g_l[b * NTILE + tile] = redl[0] + redl[1] + redl[2] + redl[3];
    }
    __syncthreads();   // p_sm visible; GEMM smem free for reuse

    // ---- partial context: cp[v] = sum_t p[t]*values[b,t0+t,v] (L2 re-read) ----
    {
        int v = tid & 255, half = tid >> 8;
        const float* vp = values + ((size_t)b * T_LEN + t0 + half * 64) * VD + v;
        float ca = 0.f;
#pragma unroll 8
        for (int t = 0; t < 64; t++) ca += p_sm[half * 64 + t] * vp[(size_t)t * VD];
        float* cacc = (float*)dsm;
        cacc[half * 256 + v] = ca;
        __syncthreads();
        if (tid < VD)
            g_cp[((b * NTILE + tile) << 8) + tid] = cacc[tid] + cacc[256 + tid];
    }
}

// ============================================================================
// K2a: stats — warp per b: global M and 1/L.  <<<1, 1024>>>
// ============================================================================
__global__ void stats_kernel()
{
    int b = threadIdx.x >> 5, lane = threadIdx.x & 31;
    float m = g_m[b * NTILE + lane];
    float l = g_l[b * NTILE + lane];
    float M = m;
#pragma unroll
    for (int o = 16; o > 0; o >>= 1) M = fmaxf(M, __shfl_xor_sync(0xffffffff, M, o));
    float lw = l * __expf(m - M);
#pragma unroll
    for (int o = 16; o > 0; o >>= 1) lw += __shfl_xor_sync(0xffffffff, lw, o);
    if (lane == 0) { g_M[b] = M; g_invL[b] = 1.0f / lw; }
}

// ============================================================================
// K2b: combine — streaming.  grid (8 chunks, B); chunk 0 also emits c.
// out layout: c [B,VD] then a [B,T]   (bv_score dropped: softmax-invariant)
// ============================================================================
__global__ void combine_kernel(float* __restrict__ out)
{
    int chunk = blockIdx.x, b = blockIdx.y, tid = threadIdx.x;
    float M = g_M[b], invL = g_invL[b];
    float* a_out = out + BATCH * VD;
    int t = chunk * 512 + tid;
    a_out[b * T_LEN + t]       = __expf(g_e[b * T_LEN + t] - M) * invL;
    a_out[b * T_LEN + t + 256] = __expf(g_e[b * T_LEN + t + 256] - M) * invL;
    if (chunk == 0) {
        float acc = 0.f;
#pragma unroll
        for (int i = 0; i < NTILE; i++)
            acc += g_cp[((b * NTILE + i) << 8) + tid] * __expf(g_m[b * NTILE + i] - M);
        out[b * VD + tid] = acc * invL;
    }
}

// ============================================================================
// launch
// ============================================================================
extern "C" void kernel_launch(void* const* d_in, const int* in_sizes, int n_in,
                              void* d_out, int out_size)
{
    const float* query  = (const float*)d_in[0];
    const float* values = (const float*)d_in[1];
    const float* Wq     = (const float*)d_in[2];
    const float* bq     = (const float*)d_in[3];
    const float* Wv     = (const float*)d_in[4];
    const float* bv     = (const float*)d_in[5];
    const float* wsc    = (const float*)d_in[6];
    // d_in[7] = bv_score: additive constant inside softmax -> no effect
    (void)in_sizes; (void)n_in; (void)out_size;
    float* out = (float*)d_out;

    cudaFuncSetAttribute(attn_main, cudaFuncAttributeMaxDynamicSharedMemorySize, DSMEM_BYTES);

    wconv_kernel<<<128, 256>>>(Wv);
    qproj_kernel<<<dim3(32, BATCH), 256>>>(query, Wq, bq, bv);
    attn_main<<<dim3(NTILE, BATCH), 512, DSMEM_BYTES>>>(values, wsc);
    stats_kernel<<<1, 1024>>>();
    combine_kernel<<<dim3(8, BATCH), 256>>>(out);
}